// round 14
// baseline (speedup 1.0000x reference)
#include <cuda_runtime.h>
#include <cstdint>
#include <cstddef>

#define BATCH 256
#define SEQT  365
#define HID   256
#define INSZ  32
#define G4    1024          // 4*HID
#define NB    128           // persistent blocks
#define NT    512           // lstm threads: 16 warps = 4 kh x 2 bh x 2 gh
#define NTX   256
#define NPAIR (HID / 2)     // 128 unit pairs (xw layout)
#define NGRP  4             // independent batch groups
#define CPG   32            // CTAs per group
#define BPG   64            // batches per group
#define UPC   8             // units per CTA

typedef unsigned long long ull;

// ---------------- scratch (static device allocations; no cudaMalloc) ----------
__device__ float4 g_xw4[(size_t)SEQT * NPAIR * 2 * BATCH];   // 382 MB, bias folded
__device__ float g_hb[2][NGRP][HID * BPG];                   // h, [buf][grp][k][b]
__device__ unsigned g_cnt[NGRP * 32];                        // per-group barrier
__device__ unsigned g_gen[NGRP * 32];

// ---------------- packed f32x2 helpers ----------------------------------------
__device__ __forceinline__ ull pack2(float lo, float hi) {
    ull r;
    asm("mov.b64 %0, {%1, %2};" : "=l"(r) : "f"(lo), "f"(hi));
    return r;
}
__device__ __forceinline__ void unpack2(ull v, float& lo, float& hi) {
    asm("mov.b64 {%0, %1}, %2;" : "=f"(lo), "=f"(hi) : "l"(v));
}
__device__ __forceinline__ ull fma2(ull a, ull b, ull c) {
    ull d;
    asm("fma.rn.f32x2 %0, %1, %2, %3;" : "=l"(d) : "l"(a), "l"(b), "l"(c));
    return d;
}
__device__ __forceinline__ ull add2(ull a, ull b) {
    ull d;
    asm("add.rn.f32x2 %0, %1, %2;" : "=l"(d) : "l"(a), "l"(b));
    return d;
}
__device__ __forceinline__ float sigf(float x) {
    return __fdividef(1.0f, 1.0f + __expf(-x));
}
__device__ __forceinline__ float tanhf_fast(float x) {
    float e = __expf(2.0f * x);
    return 1.0f - __fdividef(2.0f, e + 1.0f);
}
__device__ __forceinline__ unsigned swz(unsigned off) {
    return off ^ ((off >> 3) & 0x70);
}

// ============================================================================
// Kernel A: xw (unchanged, proven). grid (SEQT, 8).
// ============================================================================
__global__ void __launch_bounds__(NTX) xw_kernel(const float* __restrict__ x,
                                                 const float* __restrict__ w_ih,
                                                 const float* __restrict__ bias) {
    __shared__ float ws[INSZ][16][8];
    const int t   = blockIdx.x;
    const int u00 = blockIdx.y * 32;
    const int tid = threadIdx.x;

    for (int i = tid; i < INSZ * 128; i += NTX) {
        int k = i >> 7, r = i & 127, p = r >> 3, c = r & 7;
        int unit = u00 + 2 * p + (c & 1);
        ws[k][p][c] = w_ih[(size_t)k * G4 + (c >> 1) * HID + unit];
    }
    __syncthreads();

    const int b = tid;
    ull xk2[INSZ];
    const float4* xp = (const float4*)(x + ((size_t)b * SEQT + t) * INSZ);
#pragma unroll
    for (int q = 0; q < INSZ / 4; q++) {
        float4 v = xp[q];
        xk2[4 * q + 0] = pack2(v.x, v.x);
        xk2[4 * q + 1] = pack2(v.y, v.y);
        xk2[4 * q + 2] = pack2(v.z, v.z);
        xk2[4 * q + 3] = pack2(v.w, v.w);
    }

    for (int p = 0; p < 16; p++) {
        int u = u00 + 2 * p;
        ull aF = pack2(bias[u],           bias[u + 1]);
        ull aI = pack2(bias[HID + u],     bias[HID + u + 1]);
        ull aO = pack2(bias[2 * HID + u], bias[2 * HID + u + 1]);
        ull aG = pack2(bias[3 * HID + u], bias[3 * HID + u + 1]);
#pragma unroll
        for (int k = 0; k < INSZ; k++) {
            ulonglong2 wA = *(const ulonglong2*)(&ws[k][p][0]);
            ulonglong2 wB = *(const ulonglong2*)(&ws[k][p][4]);
            aF = fma2(xk2[k], wA.x, aF);
            aI = fma2(xk2[k], wA.y, aI);
            aO = fma2(xk2[k], wB.x, aO);
            aG = fma2(xk2[k], wB.y, aG);
        }
        float f0, f1, i0, i1, o0, o1, g0, g1;
        unpack2(aF, f0, f1); unpack2(aI, i0, i1);
        unpack2(aO, o0, o1); unpack2(aG, g0, g1);
        size_t base = (((size_t)t * NPAIR + (u00 / 2 + p)) * 2) * BATCH + b;
        __stcs(&g_xw4[base],         make_float4(f0, f1, i0, i1));
        __stcs(&g_xw4[base + BATCH], make_float4(o0, o1, g0, g1));
    }
}

// ============================================================================
// Kernel B: persistent LSTM. 4 groups x 32 CTAs (R13 skeleton), 16 warps.
// CTA (grp = bid>>5, ug = bid&31): units u_base = ug*8, batches grp*64..+64.
// Compute warp (kh = w&3, bh = (w>>2)&1, gh = w>>3); lane (bg = l>>2, cg = l&3).
//   Per k: 1 LDS.128 (2 gate-pairs for unit-pair cg) + 1 LDG.128 (4 batches' h)
//   -> 8 fma2. acc[4 batches][2 gates].
// sm_part layout identical to R13 ([kh][b 64][p 16]); activation (tid<256)
// and arrive-early group barrier identical to R13.
// ============================================================================
__global__ void __launch_bounds__(NT, 1) lstm_kernel(const float* __restrict__ w_hh,
                                                     const float* __restrict__ fc_w,
                                                     const float* __restrict__ fc_b,
                                                     float* __restrict__ out) {
    extern __shared__ char sm[];
    ull*   ws_u    = (ull*)sm;                 // [256 k][16 p], p = up*4+g, 32 KB
    ull*   sm_part = (ull*)(sm + 32768);       // [kh 4][b 64][p 16], 32 KB
    float* redf    = (float*)(sm + 65536);     // 2 KB

    const int bid  = blockIdx.x;
    const int grp  = bid >> 5;
    const int ug   = bid & 31;
    const int u_base = ug * UPC;
    const int tid  = threadIdx.x;
    const int l    = tid & 31;
    const int w    = tid >> 5;
    const int kh   = w & 3;              // k-quarter (64 k)
    const int bh   = (w >> 2) & 1;       // batch half (32)
    const int gh   = w >> 3;             // gate pair: 0={f,i}, 1={o,g}
    const int bg   = l >> 2;             // 0..7 (4-batch group)
    const int cg   = l & 3;              // unit-pair
    const int b0   = bh * 32 + bg * 4;   // lane's first local batch
    const int kb   = kh * 64;
    // activation mapping (tid < 256)
    const int b_l  = tid >> 2;           // local batch 0..63
    const int up   = tid & 3;            // unit-pair
    const int u0   = u_base + up * 2;
    const int b_g  = grp * BPG + b_l;

    // ---- weights: ws[k][up*4+g] = pair (w_hh[k][g*256+u0], [g*256+u0+1]) ----
    {
        float* ws_f = (float*)ws_u;
        for (int i = tid; i < HID * 32; i += NT) {
            int k = i >> 5, c = i & 31;               // c = up*8 + g*2 + e
            ws_f[i] = w_hh[(size_t)k * G4 + ((c >> 1) & 3) * HID
                           + u_base + (c >> 3) * 2 + (c & 1)];
        }
    }
    __syncthreads();

    float cc0 = 0.0f, cc1 = 0.0f;

    float* outO = out;
    float* outH = out + BATCH;
    float* outC = outH + (size_t)BATCH * SEQT * HID;

    // xw prefetch for t = 0 (activation threads only)
    const size_t xw_stride_t = (size_t)NPAIR * 2 * BATCH;
    const float4* xwp = g_xw4 + (size_t)(ug * 4 + up) * 2 * BATCH + b_g;
    float4 xA = make_float4(0, 0, 0, 0), xB = xA;
    if (tid < 256) { xA = __ldcs(xwp); xB = __ldcs(xwp + BATCH); }

    const int hoff4 = bh * 8 + bg;       // float4 index of lane's 4 batches

    for (int t = 0; t < SEQT; t++) {
        ull acc[4][2];
#pragma unroll
        for (int j = 0; j < 4; j++) { acc[j][0] = 0; acc[j][1] = 0; }

        if (t > 0) {
            const float4* hp4 = (const float4*)g_hb[t & 1][grp] + hoff4;
            float4 hb4[2][4];
#pragma unroll
            for (int kk = 0; kk < 4; kk++)
                hb4[0][kk] = __ldcg(hp4 + (size_t)(kb + kk) * 16);
#pragma unroll 4
            for (int ch = 0; ch < 16; ch++) {        // 16 chunks x 4 k
                const int cur = ch & 1, nxt = cur ^ 1;
                if (ch < 15) {
#pragma unroll
                    for (int kk = 0; kk < 4; kk++)
                        hb4[nxt][kk] = __ldcg(hp4 + (size_t)(kb + (ch + 1) * 4 + kk) * 16);
                }
#pragma unroll
                for (int kk = 0; kk < 4; kk++) {
                    const int k = kb + ch * 4 + kk;
                    ulonglong2 wv = *(const ulonglong2*)
                        (ws_u + (size_t)k * 16 + cg * 4 + gh * 2);  // gates (2g, 2g+1)
                    float4 hv = hb4[cur][kk];
                    ull h2;
                    h2 = pack2(hv.x, hv.x);
                    acc[0][0] = fma2(h2, wv.x, acc[0][0]);
                    acc[0][1] = fma2(h2, wv.y, acc[0][1]);
                    h2 = pack2(hv.y, hv.y);
                    acc[1][0] = fma2(h2, wv.x, acc[1][0]);
                    acc[1][1] = fma2(h2, wv.y, acc[1][1]);
                    h2 = pack2(hv.z, hv.z);
                    acc[2][0] = fma2(h2, wv.x, acc[2][0]);
                    acc[2][1] = fma2(h2, wv.y, acc[2][1]);
                    h2 = pack2(hv.w, hv.w);
                    acc[3][0] = fma2(h2, wv.x, acc[3][0]);
                    acc[3][1] = fma2(h2, wv.y, acc[3][1]);
                }
            }
        }

        // ---- store partials: sm_part[kh][b][cg*4 + gh*2 + g], swizzled ----
#pragma unroll
        for (int j = 0; j < 4; j++) {
            unsigned off = (unsigned)(((kh * 64 + b0 + j) * 16 + cg * 4 + gh * 2) * 8);
            *(ulonglong2*)((char*)sm_part + swz(off)) =
                make_ulonglong2(acc[j][0], acc[j][1]);
        }
        __syncthreads();

        if (tid < 256) {
            // ---- activation: thread = (b_l, up); identical to R13 ----
            ull sF = 0, sI = 0, sO = 0, sG = 0;
#pragma unroll
            for (int q = 0; q < 4; q++) {
                unsigned off = (unsigned)(((q * 64 + b_l) * 16 + up * 4) * 8);
                ulonglong2 v0 = *(const ulonglong2*)((const char*)sm_part + swz(off));
                ulonglong2 v1 = *(const ulonglong2*)((const char*)sm_part + swz(off + 16));
                sF = add2(sF, v0.x);
                sI = add2(sI, v0.y);
                sO = add2(sO, v1.x);
                sG = add2(sG, v1.y);
            }
            ull aF = add2(pack2(xA.x, xA.y), sF);
            ull aI = add2(pack2(xA.z, xA.w), sI);
            ull aO = add2(pack2(xB.x, xB.y), sO);
            ull aG = add2(pack2(xB.z, xB.w), sG);

            if (t + 1 < SEQT) {
                const float4* nx = xwp + (size_t)(t + 1) * xw_stride_t;
                xA = __ldcs(nx);
                xB = __ldcs(nx + BATCH);
            }

            float f0, f1, i0, i1, o0, o1, gg0, gg1;
            unpack2(aF, f0, f1); unpack2(aI, i0, i1);
            unpack2(aO, o0, o1); unpack2(aG, gg0, gg1);

            cc0 = sigf(f0) * cc0 + sigf(i0) * tanhf_fast(gg0);
            cc1 = sigf(f1) * cc1 + sigf(i1) * tanhf_fast(gg1);
            float h0 = sigf(o0) * tanhf_fast(cc0);
            float h1 = sigf(o1) * tanhf_fast(cc1);

            // ---- h exchange store (group-local) ----
            float* hw = g_hb[(t + 1) & 1][grp];
            hw[u0 * BPG + b_l]       = h0;
            hw[(u0 + 1) * BPG + b_l] = h1;

            // stash for output stores after arrive (reuse regs via redf? no —
            // keep in registers: stores issued below, after the arrive)
            // (h0,h1,cc0,cc1 live across the arrive)
            __syncthreads();              // drain h stores CTA-wide
            unsigned my_gen = 0;
            bool releaser = false;
            if (tid == 0) {
                volatile unsigned* genp = &g_gen[grp * 32];
                my_gen = *genp;
                __threadfence();
                if (atomicAdd(&g_cnt[grp * 32], 1u) == CPG - 1u) {
                    g_cnt[grp * 32] = 0;
                    __threadfence();
                    *genp = my_gen + 1u;
                    releaser = true;
                }
            }

            // ---- output stores overlap the barrier wait ----
            size_t ob = ((size_t)b_g * SEQT + t) * HID + u0;
            __stcs((float2*)(outH + ob), make_float2(h0, h1));
            __stcs((float2*)(outC + ob), make_float2(cc0, cc1));

            if (tid == 0 && !releaser) {
                volatile unsigned* genp = &g_gen[grp * 32];
                while (*genp == my_gen) { }
            }
            __syncthreads();
        } else {
            __syncthreads();              // matches drain sync
            __syncthreads();              // matches post-wait sync
        }
    }

    // ---- final FC: CTA handles local batches ug*2, ug*2+1 of its group ----
    const float* hl = g_hb[SEQT & 1][grp];
    float fw = (tid < 256) ? fc_w[tid] : 0.0f;
    float fb = fc_b[0];
    for (int bb = 0; bb < 2; bb++) {
        int bo = ug * 2 + bb;                      // local batch
        float v = 0.0f;
        if (tid < 256) v = __ldcg(hl + (size_t)tid * BPG + bo) * fw;
        redf[tid] = v;
        __syncthreads();
        for (int s = NT / 2; s > 0; s >>= 1) {
            if (tid < s) redf[tid] += redf[tid + s];
            __syncthreads();
        }
        if (tid == 0) outO[grp * BPG + bo] = redf[0] + fb;
        __syncthreads();
    }
}

// ============================================================================
extern "C" void kernel_launch(void* const* d_in, const int* in_sizes, int n_in,
                              void* d_out, int out_size) {
    const float* x    = (const float*)d_in[0];
    const float* w_ih = (const float*)d_in[1];
    const float* w_hh = (const float*)d_in[2];
    const float* bias = (const float*)d_in[3];
    const float* fc_w = (const float*)d_in[4];
    const float* fc_b = (const float*)d_in[5];
    float* out = (float*)d_out;

    static int configured = 0;
    if (!configured) {
        cudaFuncSetAttribute(lstm_kernel, cudaFuncAttributeMaxDynamicSharedMemorySize, 67584);
        configured = 1;
    }

    dim3 gA(SEQT, 8);
    xw_kernel<<<gA, NTX>>>(x, w_ih, bias);
    lstm_kernel<<<NB, NT, 67584>>>(w_hh, fc_w, fc_b, out);
}

// round 15
// speedup vs baseline: 1.1178x; 1.1178x over previous
#include <cuda_runtime.h>
#include <cstdint>
#include <cstddef>

#define BATCH 256
#define SEQT  365
#define HID   256
#define INSZ  32
#define G4    1024          // 4*HID
#define NB    128           // persistent blocks
#define NT    256
#define NTX   256
#define NPAIR (HID / 2)     // 128 unit pairs (xw layout)
#define NGRP  4             // independent batch groups
#define CPG   32            // CTAs per group
#define BPG   64            // batches per group
#define UPC   8             // units per CTA

typedef unsigned long long ull;

// ---------------- scratch (static device allocations; no cudaMalloc) ----------
__device__ float4 g_xw4[(size_t)SEQT * NPAIR * 2 * BATCH];   // 382 MB, bias folded
__device__ float g_hb[2][NGRP][HID * BPG];                   // h, [buf][grp][k][b]
__device__ unsigned g_cnt[NGRP * 32];                        // per-group barrier
__device__ unsigned g_gen[NGRP * 32];

// ---------------- packed f32x2 helpers ----------------------------------------
__device__ __forceinline__ ull pack2(float lo, float hi) {
    ull r;
    asm("mov.b64 %0, {%1, %2};" : "=l"(r) : "f"(lo), "f"(hi));
    return r;
}
__device__ __forceinline__ void unpack2(ull v, float& lo, float& hi) {
    asm("mov.b64 {%0, %1}, %2;" : "=f"(lo), "=f"(hi) : "l"(v));
}
__device__ __forceinline__ ull fma2(ull a, ull b, ull c) {
    ull d;
    asm("fma.rn.f32x2 %0, %1, %2, %3;" : "=l"(d) : "l"(a), "l"(b), "l"(c));
    return d;
}
__device__ __forceinline__ ull add2(ull a, ull b) {
    ull d;
    asm("add.rn.f32x2 %0, %1, %2;" : "=l"(d) : "l"(a), "l"(b));
    return d;
}
__device__ __forceinline__ float sigf(float x) {
    return __fdividef(1.0f, 1.0f + __expf(-x));
}
__device__ __forceinline__ float tanhf_fast(float x) {
    float e = __expf(2.0f * x);
    return 1.0f - __fdividef(2.0f, e + 1.0f);
}
__device__ __forceinline__ unsigned swz(unsigned off) {
    return off ^ ((off >> 3) & 0x70);
}

// ============================================================================
// Kernel A: xw (unchanged, proven). grid (SEQT, 8).
// ============================================================================
__global__ void __launch_bounds__(NTX) xw_kernel(const float* __restrict__ x,
                                                 const float* __restrict__ w_ih,
                                                 const float* __restrict__ bias) {
    __shared__ float ws[INSZ][16][8];
    const int t   = blockIdx.x;
    const int u00 = blockIdx.y * 32;
    const int tid = threadIdx.x;

    for (int i = tid; i < INSZ * 128; i += NTX) {
        int k = i >> 7, r = i & 127, p = r >> 3, c = r & 7;
        int unit = u00 + 2 * p + (c & 1);
        ws[k][p][c] = w_ih[(size_t)k * G4 + (c >> 1) * HID + unit];
    }
    __syncthreads();

    const int b = tid;
    ull xk2[INSZ];
    const float4* xp = (const float4*)(x + ((size_t)b * SEQT + t) * INSZ);
#pragma unroll
    for (int q = 0; q < INSZ / 4; q++) {
        float4 v = xp[q];
        xk2[4 * q + 0] = pack2(v.x, v.x);
        xk2[4 * q + 1] = pack2(v.y, v.y);
        xk2[4 * q + 2] = pack2(v.z, v.z);
        xk2[4 * q + 3] = pack2(v.w, v.w);
    }

    for (int p = 0; p < 16; p++) {
        int u = u00 + 2 * p;
        ull aF = pack2(bias[u],           bias[u + 1]);
        ull aI = pack2(bias[HID + u],     bias[HID + u + 1]);
        ull aO = pack2(bias[2 * HID + u], bias[2 * HID + u + 1]);
        ull aG = pack2(bias[3 * HID + u], bias[3 * HID + u + 1]);
#pragma unroll
        for (int k = 0; k < INSZ; k++) {
            ulonglong2 wA = *(const ulonglong2*)(&ws[k][p][0]);
            ulonglong2 wB = *(const ulonglong2*)(&ws[k][p][4]);
            aF = fma2(xk2[k], wA.x, aF);
            aI = fma2(xk2[k], wA.y, aI);
            aO = fma2(xk2[k], wB.x, aO);
            aG = fma2(xk2[k], wB.y, aG);
        }
        float f0, f1, i0, i1, o0, o1, g0, g1;
        unpack2(aF, f0, f1); unpack2(aI, i0, i1);
        unpack2(aO, o0, o1); unpack2(aG, g0, g1);
        size_t base = (((size_t)t * NPAIR + (u00 / 2 + p)) * 2) * BATCH + b;
        __stcs(&g_xw4[base],         make_float4(f0, f1, i0, i1));
        __stcs(&g_xw4[base + BATCH], make_float4(o0, o1, g0, g1));
    }
}

// ============================================================================
// Kernel B: persistent LSTM. 4 groups x 32 CTAs (R13 skeleton).
// CTA (grp = bid>>5, ug = bid&31): units u_base = ug*8, batches grp*64..+64.
// Compute warp = pure k-slice: kh = w (0..7), 32 k each. Warp covers all 64 b,
//   all 16 gate-pair cols. Lane (bg = l>>2: 8 batches, pg = l&3: 4 p-cols).
//   Per k: 2 LDS.128 (weights, read ONCE CTA-wide) + 2 LDG.128 (8 batches' h)
//   -> 32 fma2. acc[8 batches][4 p-cols].
// Partials sm_part[kh 8][b 64][p 16] (same row shape/swizzle as R13);
// activation (8 q-iters) and arrive-early group barrier as R13.
// ============================================================================
__global__ void __launch_bounds__(NT, 1) lstm_kernel(const float* __restrict__ w_hh,
                                                     const float* __restrict__ fc_w,
                                                     const float* __restrict__ fc_b,
                                                     float* __restrict__ out) {
    extern __shared__ char sm[];
    ull*   ws_u    = (ull*)sm;                 // [256 k][16 p], p = up*4+g, 32 KB
    ull*   sm_part = (ull*)(sm + 32768);       // [kh 8][b 64][p 16], 64 KB
    float* redf    = (float*)(sm + 98304);     // 1 KB

    const int bid  = blockIdx.x;
    const int grp  = bid >> 5;
    const int ug   = bid & 31;
    const int u_base = ug * UPC;
    const int tid  = threadIdx.x;
    const int l    = tid & 31;
    const int w    = tid >> 5;
    const int kh   = w;                  // k-slice (32 k)
    const int bg   = l >> 2;             // 0..7 (8-batch group)
    const int pg   = l & 3;              // 0..3 (4 p-cols)
    const int b0   = bg * 8;             // lane's first local batch
    const int kb   = kh * 32;
    // activation mapping
    const int b_l  = tid >> 2;           // local batch 0..63
    const int up   = tid & 3;            // unit-pair 0..3
    const int u0   = u_base + up * 2;
    const int b_g  = grp * BPG + b_l;    // global batch

    // ---- weights: ws[k][up*4+g] = pair (w_hh[k][g*256+u0], [g*256+u0+1]) ----
    {
        float* ws_f = (float*)ws_u;
        for (int i = tid; i < HID * 32; i += NT) {
            int k = i >> 5, c = i & 31;               // c = up*8 + g*2 + e
            ws_f[i] = w_hh[(size_t)k * G4 + ((c >> 1) & 3) * HID
                           + u_base + (c >> 3) * 2 + (c & 1)];
        }
    }
    __syncthreads();

    float cc0 = 0.0f, cc1 = 0.0f;

    float* outO = out;
    float* outH = out + BATCH;
    float* outC = outH + (size_t)BATCH * SEQT * HID;

    // xw prefetch for t = 0: pair_glob = ug*4 + up
    const size_t xw_stride_t = (size_t)NPAIR * 2 * BATCH;
    const float4* xwp = g_xw4 + (size_t)(ug * 4 + up) * 2 * BATCH + b_g;
    float4 xA = __ldcs(xwp);
    float4 xB = __ldcs(xwp + BATCH);

    for (int t = 0; t < SEQT; t++) {
        ull acc[8][4];
#pragma unroll
        for (int j = 0; j < 8; j++)
#pragma unroll
            for (int e = 0; e < 4; e++) acc[j][e] = 0;

        if (t > 0) {
            // lane's h: float4 pair (8 batches) per k
            const float4* hp4 = (const float4*)g_hb[t & 1][grp] + bg * 2;
            float4 hb[2][4];                 // [buf][kk*2 + half], chunk = 2 k
#pragma unroll
            for (int kk = 0; kk < 2; kk++) {
                hb[0][kk * 2]     = __ldcg(hp4 + (size_t)(kb + kk) * 16);
                hb[0][kk * 2 + 1] = __ldcg(hp4 + (size_t)(kb + kk) * 16 + 1);
            }
#pragma unroll 4
            for (int ch = 0; ch < 16; ch++) {        // 16 chunks x 2 k = 32 k
                const int cur = ch & 1, nxt = cur ^ 1;
                if (ch < 15) {
#pragma unroll
                    for (int kk = 0; kk < 2; kk++) {
                        hb[nxt][kk * 2]     = __ldcg(hp4 + (size_t)(kb + (ch + 1) * 2 + kk) * 16);
                        hb[nxt][kk * 2 + 1] = __ldcg(hp4 + (size_t)(kb + (ch + 1) * 2 + kk) * 16 + 1);
                    }
                }
#pragma unroll
                for (int kk = 0; kk < 2; kk++) {
                    const int k = kb + ch * 2 + kk;
                    const ull* wrow = ws_u + (size_t)k * 16 + pg * 4;
                    ulonglong2 w01 = *(const ulonglong2*)wrow;
                    ulonglong2 w23 = *(const ulonglong2*)(wrow + 2);
                    float4 hlo = hb[cur][kk * 2];
                    float4 hhi = hb[cur][kk * 2 + 1];
                    ull h2;
                    h2 = pack2(hlo.x, hlo.x);
                    acc[0][0] = fma2(h2, w01.x, acc[0][0]);
                    acc[0][1] = fma2(h2, w01.y, acc[0][1]);
                    acc[0][2] = fma2(h2, w23.x, acc[0][2]);
                    acc[0][3] = fma2(h2, w23.y, acc[0][3]);
                    h2 = pack2(hlo.y, hlo.y);
                    acc[1][0] = fma2(h2, w01.x, acc[1][0]);
                    acc[1][1] = fma2(h2, w01.y, acc[1][1]);
                    acc[1][2] = fma2(h2, w23.x, acc[1][2]);
                    acc[1][3] = fma2(h2, w23.y, acc[1][3]);
                    h2 = pack2(hlo.z, hlo.z);
                    acc[2][0] = fma2(h2, w01.x, acc[2][0]);
                    acc[2][1] = fma2(h2, w01.y, acc[2][1]);
                    acc[2][2] = fma2(h2, w23.x, acc[2][2]);
                    acc[2][3] = fma2(h2, w23.y, acc[2][3]);
                    h2 = pack2(hlo.w, hlo.w);
                    acc[3][0] = fma2(h2, w01.x, acc[3][0]);
                    acc[3][1] = fma2(h2, w01.y, acc[3][1]);
                    acc[3][2] = fma2(h2, w23.x, acc[3][2]);
                    acc[3][3] = fma2(h2, w23.y, acc[3][3]);
                    h2 = pack2(hhi.x, hhi.x);
                    acc[4][0] = fma2(h2, w01.x, acc[4][0]);
                    acc[4][1] = fma2(h2, w01.y, acc[4][1]);
                    acc[4][2] = fma2(h2, w23.x, acc[4][2]);
                    acc[4][3] = fma2(h2, w23.y, acc[4][3]);
                    h2 = pack2(hhi.y, hhi.y);
                    acc[5][0] = fma2(h2, w01.x, acc[5][0]);
                    acc[5][1] = fma2(h2, w01.y, acc[5][1]);
                    acc[5][2] = fma2(h2, w23.x, acc[5][2]);
                    acc[5][3] = fma2(h2, w23.y, acc[5][3]);
                    h2 = pack2(hhi.z, hhi.z);
                    acc[6][0] = fma2(h2, w01.x, acc[6][0]);
                    acc[6][1] = fma2(h2, w01.y, acc[6][1]);
                    acc[6][2] = fma2(h2, w23.x, acc[6][2]);
                    acc[6][3] = fma2(h2, w23.y, acc[6][3]);
                    h2 = pack2(hhi.w, hhi.w);
                    acc[7][0] = fma2(h2, w01.x, acc[7][0]);
                    acc[7][1] = fma2(h2, w01.y, acc[7][1]);
                    acc[7][2] = fma2(h2, w23.x, acc[7][2]);
                    acc[7][3] = fma2(h2, w23.y, acc[7][3]);
                }
            }
        }

        // ---- store partials: sm_part[kh][b0+j][pg*4 .. +3], swizzled ----
#pragma unroll
        for (int j = 0; j < 8; j++) {
            unsigned off = (unsigned)(((kh * 64 + b0 + j) * 16 + pg * 4) * 8);
            *(ulonglong2*)((char*)sm_part + swz(off)) =
                make_ulonglong2(acc[j][0], acc[j][1]);
            *(ulonglong2*)((char*)sm_part + swz(off + 16)) =
                make_ulonglong2(acc[j][2], acc[j][3]);
        }
        __syncthreads();

        // ---- activation: thread = (b_l, up); 8 k-slice partials ----
        ull sF = 0, sI = 0, sO = 0, sG = 0;
#pragma unroll
        for (int q = 0; q < 8; q++) {
            unsigned off = (unsigned)(((q * 64 + b_l) * 16 + up * 4) * 8);
            ulonglong2 v0 = *(const ulonglong2*)((const char*)sm_part + swz(off));
            ulonglong2 v1 = *(const ulonglong2*)((const char*)sm_part + swz(off + 16));
            sF = add2(sF, v0.x);
            sI = add2(sI, v0.y);
            sO = add2(sO, v1.x);
            sG = add2(sG, v1.y);
        }
        ull aF = add2(pack2(xA.x, xA.y), sF);
        ull aI = add2(pack2(xA.z, xA.w), sI);
        ull aO = add2(pack2(xB.x, xB.y), sO);
        ull aG = add2(pack2(xB.z, xB.w), sG);

        if (t + 1 < SEQT) {
            const float4* nx = xwp + (size_t)(t + 1) * xw_stride_t;
            xA = __ldcs(nx);
            xB = __ldcs(nx + BATCH);
        }

        float f0, f1, i0, i1, o0, o1, gg0, gg1;
        unpack2(aF, f0, f1); unpack2(aI, i0, i1);
        unpack2(aO, o0, o1); unpack2(aG, gg0, gg1);

        cc0 = sigf(f0) * cc0 + sigf(i0) * tanhf_fast(gg0);
        cc1 = sigf(f1) * cc1 + sigf(i1) * tanhf_fast(gg1);
        float h0 = sigf(o0) * tanhf_fast(cc0);
        float h1 = sigf(o1) * tanhf_fast(cc1);

        // ---- h exchange store (group-local) ----
        float* hw = g_hb[(t + 1) & 1][grp];
        hw[u0 * BPG + b_l]       = h0;
        hw[(u0 + 1) * BPG + b_l] = h1;

        // ---- ARRIVE early on the 32-CTA group barrier ----
        __syncthreads();
        unsigned my_gen = 0;
        bool releaser = false;
        if (tid == 0) {
            volatile unsigned* genp = &g_gen[grp * 32];
            my_gen = *genp;
            __threadfence();
            if (atomicAdd(&g_cnt[grp * 32], 1u) == CPG - 1u) {
                g_cnt[grp * 32] = 0;
                __threadfence();
                *genp = my_gen + 1u;
                releaser = true;
            }
        }

        // ---- output stores overlap the barrier wait ----
        size_t ob = ((size_t)b_g * SEQT + t) * HID + u0;
        __stcs((float2*)(outH + ob), make_float2(h0, h1));
        __stcs((float2*)(outC + ob), make_float2(cc0, cc1));

        // ---- WAIT ----
        if (tid == 0 && !releaser) {
            volatile unsigned* genp = &g_gen[grp * 32];
            while (*genp == my_gen) { }
        }
        __syncthreads();
    }

    // ---- final FC: CTA handles local batches ug*2, ug*2+1 of its group ----
    const float* hl = g_hb[SEQT & 1][grp];
    float fw = fc_w[tid];
    float fb = fc_b[0];
    for (int bb = 0; bb < 2; bb++) {
        int bo = ug * 2 + bb;                      // local batch
        redf[tid] = __ldcg(hl + (size_t)tid * BPG + bo) * fw;   // k = tid
        __syncthreads();
        for (int s = NT / 2; s > 0; s >>= 1) {
            if (tid < s) redf[tid] += redf[tid + s];
            __syncthreads();
        }
        if (tid == 0) outO[grp * BPG + bo] = redf[0] + fb;
        __syncthreads();
    }
}

// ============================================================================
extern "C" void kernel_launch(void* const* d_in, const int* in_sizes, int n_in,
                              void* d_out, int out_size) {
    const float* x    = (const float*)d_in[0];
    const float* w_ih = (const float*)d_in[1];
    const float* w_hh = (const float*)d_in[2];
    const float* bias = (const float*)d_in[3];
    const float* fc_w = (const float*)d_in[4];
    const float* fc_b = (const float*)d_in[5];
    float* out = (float*)d_out;

    static int configured = 0;
    if (!configured) {
        cudaFuncSetAttribute(lstm_kernel, cudaFuncAttributeMaxDynamicSharedMemorySize, 99328);
        configured = 1;
    }

    dim3 gA(SEQT, 8);
    xw_kernel<<<gA, NTX>>>(x, w_ih, bias);
    lstm_kernel<<<NB, NT, 99328>>>(w_hh, fc_w, fc_b, out);
}